// round 2
// baseline (speedup 1.0000x reference)
#include <cuda_runtime.h>
#include <cuda_bf16.h>
#include <cstdint>

// ===================== problem constants =====================
#define N_TOK 8192
#define DIM   256          // K
#define BT    128          // CTA tile: 128 x 128 output block
#define THREADS 512        // 16 warps: 4x4 warp grid, 32x32 per warp

__device__ __nv_bfloat16 g_emb[N_TOK * DIM];
__device__ float g_x2[N_TOK];

// ===================== helpers =====================
__device__ __forceinline__ uint32_t smem_u32(const void* p) {
    uint32_t a;
    asm("{ .reg .u64 t; cvta.to.shared.u64 t, %1; cvt.u32.u64 %0, t; }" : "=r"(a) : "l"(p));
    return a;
}

#define CP16(dst, src) \
    asm volatile("cp.async.cg.shared.global [%0], [%1], 16;" :: "r"(dst), "l"(src) : "memory")

__device__ __forceinline__ void ldsm4(uint32_t* r, uint32_t addr) {
    asm volatile("ldmatrix.sync.aligned.m8n8.x4.shared.b16 {%0,%1,%2,%3}, [%4];"
        : "=r"(r[0]), "=r"(r[1]), "=r"(r[2]), "=r"(r[3]) : "r"(addr));
}

__device__ __forceinline__ void mma16816(float* c, const uint32_t* a, uint32_t b0, uint32_t b1) {
    asm volatile("mma.sync.aligned.m16n8k16.row.col.f32.bf16.bf16.f32 "
        "{%0,%1,%2,%3}, {%4,%5,%6,%7}, {%8,%9}, {%0,%1,%2,%3};"
        : "+f"(c[0]), "+f"(c[1]), "+f"(c[2]), "+f"(c[3])
        : "r"(a[0]), "r"(a[1]), "r"(a[2]), "r"(a[3]), "r"(b0), "r"(b1));
}

// smem tile layout: row-major 512B rows (256 bf16), 16B chunks XOR-swizzled
// within each 128B group: chunk' = chunk ^ (row & 7). Conflict-free for the
// cp.async 16B stores and for ldmatrix column fetches.
__device__ __forceinline__ uint32_t sw_off(int r, int kc) {
    return (uint32_t)r * 512u + (uint32_t)((kc ^ (r & 7)) << 4);
}

// ===================== prep: fp32 -> bf16 + exact fp32 row norms =====================
__global__ void prep_kernel(const float* __restrict__ emb) {
    int row = blockIdx.x;
    int tid = threadIdx.x;  // 256 threads, one element each
    float e = emb[(size_t)row * DIM + tid];
    g_emb[(size_t)row * DIM + tid] = __float2bfloat16(e);
    float s = e * e;
#pragma unroll
    for (int o = 16; o; o >>= 1) s += __shfl_xor_sync(0xffffffffu, s, o);
    __shared__ float ws[8];
    if ((tid & 31) == 0) ws[tid >> 5] = s;
    __syncthreads();
    if (tid == 0) {
        float v = 0.f;
#pragma unroll
        for (int i = 0; i < 8; i++) v += ws[i];
        g_x2[row] = v;
    }
}

// ===================== fused GEMM (HMMA) + Poincare epilogue =====================
// smem: A tile (i rows) 64KB @0, B tile (j rows) 64KB @65536,
//       xi2 512B @131072, xj2 512B @131584  -> 132096 B total
#define SA  0u
#define SBo 65536u
#define SXI 131072u
#define SXJ 131584u
#define SMEM_TOTAL 132096

__global__ void __launch_bounds__(THREADS, 1)
poincare_kernel(float* __restrict__ out) {
    extern __shared__ char smem[];
    uint32_t sb = smem_u32(smem);

    const int tid  = threadIdx.x;
    const int lane = tid & 31;
    const int w    = tid >> 5;
    const int wm   = w >> 2;   // warp row in 4x4 grid (i dim, 32 rows)
    const int wn   = w & 3;    // warp col (j dim, 32 cols)

    const int i0 = blockIdx.y * BT;
    const int j0 = blockIdx.x * BT;

    // stage row norms
    if (tid < 128)            ((float*)(smem + SXI))[tid]       = g_x2[i0 + tid];
    else if (tid < 256)       ((float*)(smem + SXJ))[tid - 128] = g_x2[j0 + tid - 128];

    // stage A (rows i0..i0+127) and B (rows j0..j0+127), full K=256
#pragma unroll
    for (int k = 0; k < 8; k++) {
        int id = k * THREADS + tid;          // 0..4095 chunk ids
        int r  = id >> 5;                    // row 0..127
        int kc = id & 31;                    // 16B chunk 0..31
        uint32_t off = sw_off(r, kc);
        const __nv_bfloat16* sa = &g_emb[(size_t)(i0 + r) * DIM + kc * 8];
        const __nv_bfloat16* sbp = &g_emb[(size_t)(j0 + r) * DIM + kc * 8];
        CP16(sb + SA  + off, sa);
        CP16(sb + SBo + off, sbp);
    }
    asm volatile("cp.async.commit_group;" ::: "memory");
    asm volatile("cp.async.wait_all;" ::: "memory");
    __syncthreads();

    // ---------------- MMA mainloop: 16 K-steps of k16 ----------------
    float acc[2][4][4];
#pragma unroll
    for (int mt = 0; mt < 2; mt++)
#pragma unroll
        for (int nt = 0; nt < 4; nt++)
#pragma unroll
            for (int e = 0; e < 4; e++) acc[mt][nt][e] = 0.f;

    const int lrow = lane & 15;
    const int lchk = lane >> 4;

#pragma unroll 4
    for (int ks = 0; ks < 16; ks++) {
        uint32_t a[2][4], bb[2][4];
        const int kc = ks * 2 + lchk;
#pragma unroll
        for (int mt = 0; mt < 2; mt++) {
            int r = wm * 32 + mt * 16 + lrow;
            ldsm4(a[mt], sb + SA + sw_off(r, kc));
        }
#pragma unroll
        for (int h = 0; h < 2; h++) {
            int r = wn * 32 + h * 16 + lrow;
            ldsm4(bb[h], sb + SBo + sw_off(r, kc));
        }
        // bb[h]: {n(16h+0..7) k0-7, n(16h+8..15) k0-7, n(16h+0..7) k8-15, n(16h+8..15) k8-15}
#pragma unroll
        for (int mt = 0; mt < 2; mt++)
#pragma unroll
            for (int nt = 0; nt < 4; nt++)
                mma16816(acc[mt][nt], a[mt], bb[nt >> 1][nt & 1], bb[nt >> 1][(nt & 1) + 2]);
    }

    // ---------------- epilogue ----------------
    const float* xi2s = (const float*)(smem + SXI);
    const float* xj2s = (const float*)(smem + SXJ);
    const int g  = lane >> 2;
    const int tq = lane & 3;

    float2 xj2v[4];
#pragma unroll
    for (int nt = 0; nt < 4; nt++)
        xj2v[nt] = *(const float2*)(xj2s + wn * 32 + nt * 8 + tq * 2);

#pragma unroll
    for (int mt = 0; mt < 2; mt++) {
#pragma unroll
        for (int hf = 0; hf < 2; hf++) {
            const int il  = wm * 32 + mt * 16 + g + hf * 8;
            const int gi  = i0 + il;
            const float xi2 = xi2s[il];
            const float Bv  = 1.0f - xi2;
            const float Bv2 = Bv * Bv;
#pragma unroll
            for (int nt = 0; nt < 4; nt++) {
                const int jl = wn * 32 + nt * 8 + tq * 2;
                const int gj = j0 + jl;
                float2 pr, dr;
#pragma unroll
                for (int e = 0; e < 2; e++) {
                    const float dot = acc[mt][nt][hf * 2 + e];
                    const float xj2 = e ? xj2v[nt].y : xj2v[nt].x;
                    const float A   = fmaf(-2.f, dot, 1.f + xj2);          // 1 - 2dot + xj2
                    const float Dq  = fmaf(-2.f, dot, fmaf(xi2, xj2, 1.f)); // 1 - 2dot + xi2*xj2
                    const float q   = fmaf(-(Bv + Bv), dot, A * xi2);       // A*xi2 - 2B*dot
                    float num2 = fmaf(A, q, Bv2 * xj2);                     // A^2 xi2 - 2AB dot + B^2 xj2
                    num2 = fmaxf(num2, 0.f);
                    const float den = fmaxf(fabsf(Dq), 1e-15f);
                    float rd, sq, l1, l2;
                    asm("rcp.approx.f32 %0, %1;"  : "=f"(rd) : "f"(den));
                    asm("sqrt.approx.f32 %0, %1;" : "=f"(sq) : "f"(num2));
                    const float x = fminf(sq * rd, 1.0f - 1e-7f);
                    float p = fmaf(-0.5f, x, 0.5f);          // sigmoid(-dist) == (1-x)/2 exactly (c=1)
                    asm("lg2.approx.f32 %0, %1;" : "=f"(l1) : "f"(1.f + x));
                    asm("lg2.approx.f32 %0, %1;" : "=f"(l2) : "f"(1.f - x));
                    float d = (l1 - l2) * 0.6931471805599453f; // ln((1+x)/(1-x)) = 2*artanh(x)
                    if (gi == gj + e) { p = 0.f; d = 0.f; }    // diagonal mask
                    if (e) { pr.y = p; dr.y = d; } else { pr.x = p; dr.x = d; }
                }
                const size_t o = (size_t)gi * N_TOK + gj;
                *(float2*)(out + o)                           = pr;
                *(float2*)(out + o + (size_t)N_TOK * N_TOK)   = dr;
            }
        }
    }
}

// ===================== launch =====================
extern "C" void kernel_launch(void* const* d_in, const int* in_sizes, int n_in,
                              void* d_out, int out_size) {
    const float* emb = (const float*)d_in[0];
    float* out = (float*)d_out;

    cudaFuncSetAttribute(poincare_kernel, cudaFuncAttributeMaxDynamicSharedMemorySize, SMEM_TOTAL);

    prep_kernel<<<N_TOK, DIM>>>(emb);

    dim3 grid(N_TOK / BT, N_TOK / BT);   // 64 x 64 tiles
    poincare_kernel<<<grid, THREADS, SMEM_TOTAL>>>(out);
}

// round 3
// speedup vs baseline: 1.2722x; 1.2722x over previous
#include <cuda_runtime.h>
#include <cuda_bf16.h>
#include <cstdint>

// ===================== problem constants =====================
#define N_TOK 8192
#define DIM   256          // K
#define BT    128          // CTA tile: 128 x 128 output block
#define THREADS 512        // 16 warps: 4x4 warp grid, 32x32 per warp
#define NT    (N_TOK / BT) // 64 tiles per dim
#define NTILES_TRI (NT * (NT + 1) / 2)  // 2080

__device__ __nv_bfloat16 g_emb[N_TOK * DIM];
__device__ float g_x2[N_TOK];

// ===================== helpers =====================
__device__ __forceinline__ uint32_t smem_u32(const void* p) {
    uint32_t a;
    asm("{ .reg .u64 t; cvta.to.shared.u64 t, %1; cvt.u32.u64 %0, t; }" : "=r"(a) : "l"(p));
    return a;
}

#define CP16(dst, src) \
    asm volatile("cp.async.cg.shared.global [%0], [%1], 16;" :: "r"(dst), "l"(src) : "memory")

__device__ __forceinline__ void ldsm4(uint32_t* r, uint32_t addr) {
    asm volatile("ldmatrix.sync.aligned.m8n8.x4.shared.b16 {%0,%1,%2,%3}, [%4];"
        : "=r"(r[0]), "=r"(r[1]), "=r"(r[2]), "=r"(r[3]) : "r"(addr));
}

__device__ __forceinline__ void mma16816(float* c, const uint32_t* a, uint32_t b0, uint32_t b1) {
    asm volatile("mma.sync.aligned.m16n8k16.row.col.f32.bf16.bf16.f32 "
        "{%0,%1,%2,%3}, {%4,%5,%6,%7}, {%8,%9}, {%0,%1,%2,%3};"
        : "+f"(c[0]), "+f"(c[1]), "+f"(c[2]), "+f"(c[3])
        : "r"(a[0]), "r"(a[1]), "r"(a[2]), "r"(a[3]), "r"(b0), "r"(b1));
}

// smem tile layout: row-major 512B rows (256 bf16), 16B chunks XOR-swizzled
// within each 128B group: chunk' = chunk ^ (row & 7). Conflict-free for the
// cp.async 16B stores and the ldmatrix fetches.
__device__ __forceinline__ uint32_t sw_off(int r, int kc) {
    return (uint32_t)r * 512u + (uint32_t)((kc ^ (r & 7)) << 4);
}

// ===================== prep: fp32 -> bf16 + exact fp32 row norms =====================
__global__ void prep_kernel(const float* __restrict__ emb) {
    int row = blockIdx.x;
    int tid = threadIdx.x;  // 256 threads, one element each
    float e = emb[(size_t)row * DIM + tid];
    g_emb[(size_t)row * DIM + tid] = __float2bfloat16(e);
    float s = e * e;
#pragma unroll
    for (int o = 16; o; o >>= 1) s += __shfl_xor_sync(0xffffffffu, s, o);
    __shared__ float ws[8];
    if ((tid & 31) == 0) ws[tid >> 5] = s;
    __syncthreads();
    if (tid == 0) {
        float v = 0.f;
#pragma unroll
        for (int i = 0; i < 8; i++) v += ws[i];
        g_x2[row] = v;
    }
}

// ===================== smem layout =====================
// Phase 1 (load + MMA): A tile 64KB @0, B tile 64KB @65536
// Phase 2 (epilogue + transpose): probs staging 68096B @0, dists @68096
//   staging row stride = 133 floats -> conflict-free STS (5g+2tq distinct mod 32)
//   and conflict-free column LDS (stride 5 mod 32, coprime).
// Row norms live beyond both regions.
#define SA   0u
#define SBo  65536u
#define SP   0u
#define SD   68096u
#define SXI  136192u
#define SXJ  136704u
#define SMEM_TOTAL 137216
#define PSTRIDE 133

__global__ void __launch_bounds__(THREADS, 1)
poincare_kernel(float* __restrict__ out) {
    extern __shared__ char smem[];
    uint32_t sb = smem_u32(smem);

    const int tid  = threadIdx.x;
    const int lane = tid & 31;
    const int w    = tid >> 5;
    const int wm   = w >> 2;   // warp row in 4x4 grid (i dim, 32 rows)
    const int wn   = w & 3;    // warp col (j dim, 32 cols)

    // ---- decode upper-triangular tile index: ti <= tj ----
    const int t = blockIdx.x;
    int ti = (int)floorf(((float)(2 * NT + 1)
              - sqrtf((float)((2 * NT + 1) * (2 * NT + 1)) - 8.0f * (float)t)) * 0.5f);
    while (ti > 0 && ti * NT - ti * (ti - 1) / 2 > t) ti--;
    while ((ti + 1) * NT - (ti + 1) * ti / 2 <= t) ti++;
    const int tj = ti + (t - (ti * NT - ti * (ti - 1) / 2));

    const int i0 = ti * BT;
    const int j0 = tj * BT;
    const bool offdiag = (ti != tj);

    // stage row norms
    if (tid < 128)            ((float*)(smem + SXI))[tid]       = g_x2[i0 + tid];
    else if (tid < 256)       ((float*)(smem + SXJ))[tid - 128] = g_x2[j0 + tid - 128];

    // stage A (rows i0..) and B (rows j0..), full K=256
#pragma unroll
    for (int k = 0; k < 8; k++) {
        int id = k * THREADS + tid;          // 0..4095 chunk ids
        int r  = id >> 5;                    // row 0..127
        int kc = id & 31;                    // 16B chunk 0..31
        uint32_t off = sw_off(r, kc);
        CP16(sb + SA  + off, &g_emb[(size_t)(i0 + r) * DIM + kc * 8]);
        CP16(sb + SBo + off, &g_emb[(size_t)(j0 + r) * DIM + kc * 8]);
    }
    asm volatile("cp.async.commit_group;" ::: "memory");
    asm volatile("cp.async.wait_all;" ::: "memory");
    __syncthreads();

    // ---------------- MMA mainloop: 16 K-steps of k16 ----------------
    float acc[2][4][4];
#pragma unroll
    for (int mt = 0; mt < 2; mt++)
#pragma unroll
        for (int nt = 0; nt < 4; nt++)
#pragma unroll
            for (int e = 0; e < 4; e++) acc[mt][nt][e] = 0.f;

    const int lrow = lane & 15;
    const int lchk = lane >> 4;

#pragma unroll
    for (int ks = 0; ks < 16; ks++) {
        uint32_t a[2][4], bb[2][4];
        const int kc = ks * 2 + lchk;
#pragma unroll
        for (int mt = 0; mt < 2; mt++)
            ldsm4(a[mt], sb + SA + sw_off(wm * 32 + mt * 16 + lrow, kc));
#pragma unroll
        for (int h = 0; h < 2; h++)
            ldsm4(bb[h], sb + SBo + sw_off(wn * 32 + h * 16 + lrow, kc));
#pragma unroll
        for (int mt = 0; mt < 2; mt++)
#pragma unroll
            for (int nt = 0; nt < 4; nt++)
                mma16816(acc[mt][nt], a[mt], bb[nt >> 1][nt & 1], bb[nt >> 1][(nt & 1) + 2]);
    }

    // all warps done reading A/B smem before staging overwrites it
    __syncthreads();

    // ---------------- epilogue: direct writes + transpose staging ----------------
    const float* xi2s = (const float*)(smem + SXI);
    const float* xj2s = (const float*)(smem + SXJ);
    float* sp = (float*)(smem + SP);
    float* sd = (float*)(smem + SD);
    const int g  = lane >> 2;
    const int tq = lane & 3;

    float2 xj2v[4];
#pragma unroll
    for (int nt = 0; nt < 4; nt++)
        xj2v[nt] = *(const float2*)(xj2s + wn * 32 + nt * 8 + tq * 2);

#pragma unroll
    for (int mt = 0; mt < 2; mt++) {
#pragma unroll
        for (int hf = 0; hf < 2; hf++) {
            const int il  = wm * 32 + mt * 16 + g + hf * 8;
            const int gi  = i0 + il;
            const float xi2 = xi2s[il];
            const float Bv  = 1.0f - xi2;
            const float Bv2 = Bv * Bv;
#pragma unroll
            for (int nt = 0; nt < 4; nt++) {
                const int jl = wn * 32 + nt * 8 + tq * 2;
                const int gj = j0 + jl;
                float2 pr, dr;
#pragma unroll
                for (int e = 0; e < 2; e++) {
                    const float dot = acc[mt][nt][hf * 2 + e];
                    const float xj2 = e ? xj2v[nt].y : xj2v[nt].x;
                    const float A   = fmaf(-2.f, dot, 1.f + xj2);           // 1 - 2dot + xj2
                    const float Dq  = fmaf(-2.f, dot, fmaf(xi2, xj2, 1.f)); // 1 - 2dot + xi2*xj2
                    const float q   = fmaf(-(Bv + Bv), dot, A * xi2);       // A*xi2 - 2B*dot
                    float num2 = fmaf(A, q, Bv2 * xj2);                     // A^2 xi2 - 2AB dot + B^2 xj2
                    num2 = fmaxf(num2, 0.f);
                    const float den = fmaxf(fabsf(Dq), 1e-15f);
                    float rd, sq, l1, l2;
                    asm("rcp.approx.f32 %0, %1;"  : "=f"(rd) : "f"(den));
                    asm("sqrt.approx.f32 %0, %1;" : "=f"(sq) : "f"(num2));
                    const float x = fminf(sq * rd, 1.0f - 1e-7f);
                    float p = fmaf(-0.5f, x, 0.5f);            // sigmoid(-dist) == (1-x)/2 (c=1)
                    asm("lg2.approx.f32 %0, %1;" : "=f"(l1) : "f"(1.f + x));
                    asm("lg2.approx.f32 %0, %1;" : "=f"(l2) : "f"(1.f - x));
                    float d = (l1 - l2) * 0.6931471805599453f; // 2*artanh(x)
                    if (gi == gj + e) { p = 0.f; d = 0.f; }    // diagonal mask
                    if (e) { pr.y = p; dr.y = d; } else { pr.x = p; dr.x = d; }
                    sp[il * PSTRIDE + jl + e] = p;             // transpose staging
                    sd[il * PSTRIDE + jl + e] = d;
                }
                const size_t o = (size_t)gi * N_TOK + gj;
                *(float2*)(out + o)                         = pr;
                *(float2*)(out + o + (size_t)N_TOK * N_TOK) = dr;
            }
        }
    }

    // ---------------- mirrored block (coalesced) ----------------
    if (offdiag) {
        __syncthreads();
#pragma unroll 4
        for (int k = 0; k < 32; k++) {
            int id = k * THREADS + tid;       // 0..16383
            int r  = id >> 7;                 // local j row 0..127
            int c  = id & 127;                // local i col 0..127
            const size_t o = (size_t)(j0 + r) * N_TOK + (i0 + c);
            out[o]                         = sp[c * PSTRIDE + r];
            out[o + (size_t)N_TOK * N_TOK] = sd[c * PSTRIDE + r];
        }
    }
}

// ===================== launch =====================
extern "C" void kernel_launch(void* const* d_in, const int* in_sizes, int n_in,
                              void* d_out, int out_size) {
    const float* emb = (const float*)d_in[0];
    float* out = (float*)d_out;

    cudaFuncSetAttribute(poincare_kernel, cudaFuncAttributeMaxDynamicSharedMemorySize, SMEM_TOTAL);

    prep_kernel<<<N_TOK, DIM>>>(emb);

    poincare_kernel<<<NTILES_TRI, THREADS, SMEM_TOTAL>>>(out);
}

// round 4
// speedup vs baseline: 1.5584x; 1.2250x over previous
#include <cuda_runtime.h>
#include <cuda_bf16.h>
#include <cstdint>

// ===================== problem constants =====================
#define N_TOK 8192
#define DIM   256          // K
#define BTI   128          // CTA tile rows (i)
#define BTJ   64           // CTA tile cols (j)
#define THREADS 256        // 8 warps: 4(i) x 2(j) warp grid, 32x32 per warp
#define NTI   (N_TOK / BTI)            // 64
#define NTJ   (N_TOK / BTJ)            // 128
#define NTILES 4160                    // sum_{ti<64} (128 - 2*ti)

__device__ __nv_bfloat16 g_emb[N_TOK * DIM];
__device__ float g_x2[N_TOK];

// ===================== helpers =====================
__device__ __forceinline__ uint32_t smem_u32(const void* p) {
    uint32_t a;
    asm("{ .reg .u64 t; cvta.to.shared.u64 t, %1; cvt.u32.u64 %0, t; }" : "=r"(a) : "l"(p));
    return a;
}

#define CP16(dst, src) \
    asm volatile("cp.async.cg.shared.global [%0], [%1], 16;" :: "r"(dst), "l"(src) : "memory")

__device__ __forceinline__ void ldsm4(uint32_t* r, uint32_t addr) {
    asm volatile("ldmatrix.sync.aligned.m8n8.x4.shared.b16 {%0,%1,%2,%3}, [%4];"
        : "=r"(r[0]), "=r"(r[1]), "=r"(r[2]), "=r"(r[3]) : "r"(addr));
}

__device__ __forceinline__ void mma16816(float* c, const uint32_t* a, uint32_t b0, uint32_t b1) {
    asm volatile("mma.sync.aligned.m16n8k16.row.col.f32.bf16.bf16.f32 "
        "{%0,%1,%2,%3}, {%4,%5,%6,%7}, {%8,%9}, {%0,%1,%2,%3};"
        : "+f"(c[0]), "+f"(c[1]), "+f"(c[2]), "+f"(c[3])
        : "r"(a[0]), "r"(a[1]), "r"(a[2]), "r"(a[3]), "r"(b0), "r"(b1));
}

// smem operand layout: row-major 512B rows (256 bf16), 16B chunks XOR-swizzled.
__device__ __forceinline__ uint32_t sw_off(int r, int kc) {
    return (uint32_t)r * 512u + (uint32_t)((kc ^ (r & 7)) << 4);
}

// ===================== prep: fp32 -> bf16 + exact fp32 row norms =====================
// 1 warp per row; float4 loads, packed bf16x2 stores.
__global__ void prep_kernel(const float* __restrict__ emb) {
    const int row  = (blockIdx.x << 3) + (threadIdx.x >> 5);
    const int lane = threadIdx.x & 31;
    const float4* src = (const float4*)(emb + (size_t)row * DIM + lane * 8);
    float4 v0 = src[0], v1 = src[1];
    float s = v0.x * v0.x;
    s = fmaf(v0.y, v0.y, s); s = fmaf(v0.z, v0.z, s); s = fmaf(v0.w, v0.w, s);
    s = fmaf(v1.x, v1.x, s); s = fmaf(v1.y, v1.y, s);
    s = fmaf(v1.z, v1.z, s); s = fmaf(v1.w, v1.w, s);
#pragma unroll
    for (int o = 16; o; o >>= 1) s += __shfl_xor_sync(0xffffffffu, s, o);

    __nv_bfloat162 b0 = __floats2bfloat162_rn(v0.x, v0.y);
    __nv_bfloat162 b1 = __floats2bfloat162_rn(v0.z, v0.w);
    __nv_bfloat162 b2 = __floats2bfloat162_rn(v1.x, v1.y);
    __nv_bfloat162 b3 = __floats2bfloat162_rn(v1.z, v1.w);
    uint4 packed;
    packed.x = *(uint32_t*)&b0; packed.y = *(uint32_t*)&b1;
    packed.z = *(uint32_t*)&b2; packed.w = *(uint32_t*)&b3;
    *(uint4*)(g_emb + (size_t)row * DIM + lane * 8) = packed;
    if (lane == 0) g_x2[row] = s;
}

// ===================== smem layout (per CTA) =====================
// Phase 1: A tile (128 rows) 64KB @0, B tile (64 rows) 32KB @65536  -> 98304
// Phase 2: staging probs @0 (128x69 fl = 35328B), dists @35328      -> 70656
// Norms beyond both: xi2 @98304 (512B), xj2 @98816 (256B). Total 99328.
#define SA   0u
#define SBo  65536u
#define SP   0u
#define SD   35328u
#define SXI  98304u
#define SXJ  98816u
#define SMEM_TOTAL 99328
#define PSTRIDE 69   // 69 mod 32 = 5, coprime -> conflict-free column access

__global__ void __launch_bounds__(THREADS, 2)
poincare_kernel(float* __restrict__ out) {
    extern __shared__ char smem[];
    uint32_t sb = smem_u32(smem);

    const int tid  = threadIdx.x;
    const int lane = tid & 31;
    const int w    = tid >> 5;
    const int wm   = w >> 1;   // warp row in 4x2 grid (i dim, 32 rows each)
    const int wn   = w & 1;    // warp col (j dim, 32 cols each)

    // ---- decode upper-tri rectangular tile: ti in [0,64), tjj in [2ti,128) ----
    const int t = blockIdx.x;
    int ti = (int)((129.0f - sqrtf(16641.0f - 4.0f * (float)t)) * 0.5f);
    while (ti > 0 && ti * (129 - ti) > t) ti--;
    while ((ti + 1) * (128 - ti) <= t) ti++;
    const int tjj = 2 * ti + (t - ti * (129 - ti));

    const int i0 = ti * BTI;
    const int j0 = tjj * BTJ;
    const bool band = (j0 < i0 + BTI);   // tile straddles/touches the diagonal

    // stage row norms
    if (tid < 128)           ((float*)(smem + SXI))[tid]       = g_x2[i0 + tid];
    else if (tid < 192)      ((float*)(smem + SXJ))[tid - 128] = g_x2[j0 + tid - 128];

    // stage A (128 rows) and B (64 rows), full K=256
#pragma unroll
    for (int k = 0; k < 16; k++) {           // A: 4096 16B-chunks
        int id = k * THREADS + tid;
        int r = id >> 5, kc = id & 31;
        CP16(sb + SA + sw_off(r, kc), &g_emb[(size_t)(i0 + r) * DIM + kc * 8]);
    }
#pragma unroll
    for (int k = 0; k < 8; k++) {            // B: 2048 16B-chunks
        int id = k * THREADS + tid;
        int r = id >> 5, kc = id & 31;
        CP16(sb + SBo + sw_off(r, kc), &g_emb[(size_t)(j0 + r) * DIM + kc * 8]);
    }
    asm volatile("cp.async.commit_group;" ::: "memory");
    asm volatile("cp.async.wait_all;" ::: "memory");
    __syncthreads();

    // ---------------- MMA mainloop: 16 K-steps of k16 ----------------
    float acc[2][4][4];
#pragma unroll
    for (int mt = 0; mt < 2; mt++)
#pragma unroll
        for (int nt = 0; nt < 4; nt++)
#pragma unroll
            for (int e = 0; e < 4; e++) acc[mt][nt][e] = 0.f;

    const int lrow = lane & 15;
    const int lchk = lane >> 4;

#pragma unroll
    for (int ks = 0; ks < 16; ks++) {
        uint32_t a[2][4], bb[2][4];
        const int kc = ks * 2 + lchk;
#pragma unroll
        for (int mt = 0; mt < 2; mt++)
            ldsm4(a[mt], sb + SA + sw_off(wm * 32 + mt * 16 + lrow, kc));
#pragma unroll
        for (int h = 0; h < 2; h++)
            ldsm4(bb[h], sb + SBo + sw_off(wn * 32 + h * 16 + lrow, kc));
#pragma unroll
        for (int mt = 0; mt < 2; mt++)
#pragma unroll
            for (int nt = 0; nt < 4; nt++)
                mma16816(acc[mt][nt], a[mt], bb[nt >> 1][nt & 1], bb[nt >> 1][(nt & 1) + 2]);
    }

    __syncthreads();   // operands no longer needed; staging may overwrite

    // ---------------- epilogue: direct writes + transpose staging ----------------
    const float* xi2s = (const float*)(smem + SXI);
    const float* xj2s = (const float*)(smem + SXJ);
    float* sp = (float*)(smem + SP);
    float* sd = (float*)(smem + SD);
    const int g  = lane >> 2;
    const int tq = lane & 3;

    float2 xj2v[4];
#pragma unroll
    for (int nt = 0; nt < 4; nt++)
        xj2v[nt] = *(const float2*)(xj2s + wn * 32 + nt * 8 + tq * 2);

#pragma unroll
    for (int mt = 0; mt < 2; mt++) {
#pragma unroll
        for (int hf = 0; hf < 2; hf++) {
            const int il  = wm * 32 + mt * 16 + g + hf * 8;
            const int gi  = i0 + il;
            const float xi2 = xi2s[il];
            const float Bv  = 1.0f - xi2;
            const float Bv2 = Bv * Bv;
#pragma unroll
            for (int nt = 0; nt < 4; nt++) {
                const int jl = wn * 32 + nt * 8 + tq * 2;
                const int gj = j0 + jl;
                float2 pr, dr;
#pragma unroll
                for (int e = 0; e < 2; e++) {
                    const float dot = acc[mt][nt][hf * 2 + e];
                    const float xj2 = e ? xj2v[nt].y : xj2v[nt].x;
                    const float A   = fmaf(-2.f, dot, 1.f + xj2);           // 1 - 2dot + xj2
                    const float Dq  = fmaf(-2.f, dot, fmaf(xi2, xj2, 1.f)); // 1 - 2dot + xi2*xj2
                    const float q   = fmaf(-(Bv + Bv), dot, A * xi2);       // A*xi2 - 2B*dot
                    float num2 = fmaf(A, q, Bv2 * xj2);
                    num2 = fmaxf(num2, 0.f);
                    const float den = fmaxf(fabsf(Dq), 1e-15f);
                    float rd, sq, l1, l2;
                    asm("rcp.approx.f32 %0, %1;"  : "=f"(rd) : "f"(den));
                    asm("sqrt.approx.f32 %0, %1;" : "=f"(sq) : "f"(num2));
                    const float x = fminf(sq * rd, 1.0f - 1e-7f);
                    float p = fmaf(-0.5f, x, 0.5f);            // sigmoid(-dist) == (1-x)/2 (c=1)
                    asm("lg2.approx.f32 %0, %1;" : "=f"(l1) : "f"(1.f + x));
                    asm("lg2.approx.f32 %0, %1;" : "=f"(l2) : "f"(1.f - x));
                    float d = (l1 - l2) * 0.6931471805599453f; // 2*artanh(x)
                    if (gi == gj + e) { p = 0.f; d = 0.f; }    // diagonal mask
                    if (e) { pr.y = p; dr.y = d; } else { pr.x = p; dr.x = d; }
                    sp[il * PSTRIDE + jl + e] = p;             // transpose staging
                    sd[il * PSTRIDE + jl + e] = d;
                }
                const size_t o = (size_t)gi * N_TOK + gj;
                if (!band || gj >= gi) {
                    *(float2*)(out + o)                         = pr;
                    *(float2*)(out + o + (size_t)N_TOK * N_TOK) = dr;
                } else if (gj + 1 == gi) {   // pair straddles: write diag elem only
                    out[o + 1]                         = pr.y;
                    out[o + 1 + (size_t)N_TOK * N_TOK] = dr.y;
                }
            }
        }
    }

    // ---------------- mirrored block (coalesced) ----------------
    __syncthreads();
    if (!band) {
#pragma unroll 4
        for (int k = 0; k < 32; k++) {
            int id = k * THREADS + tid;       // 0..8191
            int r  = id >> 7;                 // local j row 0..63
            int c  = id & 127;                // local i col 0..127
            const size_t o = (size_t)(j0 + r) * N_TOK + (i0 + c);
            out[o]                         = sp[c * PSTRIDE + r];
            out[o + (size_t)N_TOK * N_TOK] = sd[c * PSTRIDE + r];
        }
    } else {
#pragma unroll 4
        for (int k = 0; k < 32; k++) {
            int id = k * THREADS + tid;
            int r  = id >> 7;
            int c  = id & 127;
            if (j0 + r > i0 + c) {            // strictly below diagonal
                const size_t o = (size_t)(j0 + r) * N_TOK + (i0 + c);
                out[o]                         = sp[c * PSTRIDE + r];
                out[o + (size_t)N_TOK * N_TOK] = sd[c * PSTRIDE + r];
            }
        }
    }
}

// ===================== launch =====================
extern "C" void kernel_launch(void* const* d_in, const int* in_sizes, int n_in,
                              void* d_out, int out_size) {
    const float* emb = (const float*)d_in[0];
    float* out = (float*)d_out;

    cudaFuncSetAttribute(poincare_kernel, cudaFuncAttributeMaxDynamicSharedMemorySize, SMEM_TOTAL);

    prep_kernel<<<N_TOK / 8, 256>>>(emb);

    poincare_kernel<<<NTILES, THREADS, SMEM_TOTAL>>>(out);
}